// round 2
// baseline (speedup 1.0000x reference)
#include <cuda_runtime.h>
#include <cuda_bf16.h>
#include <math.h>

// ---------------------------------------------------------------------------
// HPNETLoss: out[0] = sum(weight * (conf - conf_gt)^2) / 65536   (16.7M elems)
//            out[1] = sum(mask * (d - d_ann)^2) / N              (N = 8192)
//            out[2] = sum(mask * min(n1, n2)) / N
// ---------------------------------------------------------------------------

__global__ void hp_init_out(float* out) {
    if (threadIdx.x < 3) out[threadIdx.x] = 0.0f;
}

__device__ __forceinline__ float block_reduce_sum(float v, float* smem) {
    #pragma unroll
    for (int off = 16; off > 0; off >>= 1)
        v += __shfl_down_sync(0xFFFFFFFFu, v, off);
    int lane = threadIdx.x & 31;
    int wid  = threadIdx.x >> 5;
    if (lane == 0) smem[wid] = v;
    __syncthreads();
    int nwarps = (blockDim.x + 31) >> 5;
    v = (threadIdx.x < nwarps) ? smem[threadIdx.x] : 0.0f;
    if (wid == 0) {
        #pragma unroll
        for (int off = 16; off > 0; off >>= 1)
            v += __shfl_down_sync(0xFFFFFFFFu, v, off);
    }
    return v;  // valid in thread 0
}

__global__ void hp_conf_loss(const float4* __restrict__ conf,
                             const float4* __restrict__ gt,
                             const float4* __restrict__ wgt,
                             float* __restrict__ out, int n4) {
    float acc = 0.0f;
    int stride = gridDim.x * blockDim.x;
    for (int i = blockIdx.x * blockDim.x + threadIdx.x; i < n4; i += stride) {
        float4 c = conf[i];
        float4 g = gt[i];
        float4 w = wgt[i];
        float d0 = c.x - g.x, d1 = c.y - g.y, d2 = c.z - g.z, d3 = c.w - g.w;
        acc = fmaf(w.x, d0 * d0, acc);
        acc = fmaf(w.y, d1 * d1, acc);
        acc = fmaf(w.z, d2 * d2, acc);
        acc = fmaf(w.w, d3 * d3, acc);
    }
    __shared__ float smem[32];
    float total = block_reduce_sum(acc, smem);
    if (threadIdx.x == 0)
        atomicAdd(out, total * (1.0f / 65536.0f));
}

__device__ __forceinline__ void quat2mat9(float q0, float q1, float q2, float q3,
                                          float* m) {
    m[0] = q0*q0 + q1*q1 - q2*q2 - q3*q3;
    m[1] = 2.0f * (q1*q2 - q0*q3);
    m[2] = 2.0f * (q1*q3 + q0*q2);
    m[3] = 2.0f * (q1*q2 + q0*q3);
    m[4] = q0*q0 - q1*q1 + q2*q2 - q3*q3;
    m[5] = 2.0f * (q2*q3 - q0*q1);
    m[6] = 2.0f * (q1*q3 - q0*q2);
    m[7] = 2.0f * (q2*q3 + q0*q1);
    m[8] = q0*q0 - q1*q1 - q2*q2 + q3*q3;
}

__global__ void hp_ann_loss(const float* __restrict__ dr,     // [N,5]
                            const float* __restrict__ ann,    // [N,5]
                            const int* __restrict__ flags,    // [N] bool-as-int32
                            float* __restrict__ out, int N) {
    int i = blockIdx.x * blockDim.x + threadIdx.x;
    float dsum = 0.0f, rsum = 0.0f;
    if (i < N && flags[i] != 0) {
        const float* drp  = dr  + i * 5;
        const float* annp = ann + i * 5;
        float dd = drp[0] - annp[0];
        dsum = dd * dd;

        // m_pred from ann_values quaternion (NOT normalized)
        float mp[9];
        quat2mat9(annp[1], annp[2], annp[3], annp[4], mp);

        // m_gt from normalized depth_and_rotation quaternion
        float q0 = drp[1], q1 = drp[2], q2 = drp[3], q3 = drp[4];
        float inv = rsqrtf(q0*q0 + q1*q1 + q2*q2 + q3*q3);
        float mg[9];
        quat2mat9(q0 * inv, q1 * inv, q2 * inv, q3 * inv, mg);

        // n1: || m_gt - m_pred ||_F
        // n2: || m_gt - m_pred @ RY ||_F, RY = diag(-1, 1, -1)
        //     -> columns 0 and 2 of m_pred negated
        float s1 = 0.0f, s2 = 0.0f;
        #pragma unroll
        for (int k = 0; k < 9; k++) {
            int col = k % 3;
            float e1 = mg[k] - mp[k];
            float mpr = (col == 1) ? mp[k] : -mp[k];
            float e2 = mg[k] - mpr;
            s1 = fmaf(e1, e1, s1);
            s2 = fmaf(e2, e2, s2);
        }
        float n1 = sqrtf(s1), n2 = sqrtf(s2);
        rsum = fminf(n1, n2);
    }
    __shared__ float smem[32];
    float dtot = block_reduce_sum(dsum, smem);
    __syncthreads();
    float rtot = block_reduce_sum(rsum, smem);
    if (threadIdx.x == 0) {
        float invN = 1.0f / (float)N;
        atomicAdd(out + 1, dtot * invN);
        atomicAdd(out + 2, rtot * invN);
    }
}

extern "C" void kernel_launch(void* const* d_in, const int* in_sizes, int n_in,
                              void* d_out, int out_size) {
    const float* conf = (const float*)d_in[0];   // (256,1,256,256)
    const float* gt   = (const float*)d_in[1];   // (256,1,256,256)
    const float* wgt  = (const float*)d_in[2];   // (256,256,256)
    const float* dr   = (const float*)d_in[3];   // (8192,5)
    const float* ann  = (const float*)d_in[4];   // (8192,5)
    const int* flags  = (const int*)d_in[5];     // (8192,) bool as int32

    float* out = (float*)d_out;
    int n_conf = in_sizes[0];      // 16777216
    int n4 = n_conf >> 2;
    int N = in_sizes[5];           // 8192

    hp_init_out<<<1, 32>>>(out);

    const int TPB = 256;
    int blocks = 148 * 8;          // ~8 waves of 148 SMs worth of threads
    hp_conf_loss<<<blocks, TPB>>>((const float4*)conf, (const float4*)gt,
                                  (const float4*)wgt, out, n4);

    hp_ann_loss<<<(N + TPB - 1) / TPB, TPB>>>(dr, ann, flags, out, N);
}

// round 3
// speedup vs baseline: 1.0245x; 1.0245x over previous
#include <cuda_runtime.h>
#include <cuda_bf16.h>
#include <math.h>

// ---------------------------------------------------------------------------
// HPNETLoss fused two-launch version.
//   out[0] = sum(weight * (conf - conf_gt)^2) / 65536   (16.7M elems, HBM-bound)
//   out[1] = sum(mask * (d - d_ann)^2) / N              (N = 8192)
//   out[2] = sum(mask * min(n1, n2)) / N
// Kernel 1: conf blocks write per-block partials; tail blocks do ann work.
// Kernel 2: one block reduces all partials -> out. No atomics, no init kernel.
// ---------------------------------------------------------------------------

#define NBLK_CONF 1184   // 148 SMs * 8
#define NBLK_ANN  32     // 32 * 256 = 8192 threads, one per ann item
#define TPB       256

__device__ float g_conf_part[NBLK_CONF];
__device__ float g_depth_part[NBLK_ANN];
__device__ float g_rot_part[NBLK_ANN];

__device__ __forceinline__ float block_reduce_sum(float v, float* smem) {
    #pragma unroll
    for (int off = 16; off > 0; off >>= 1)
        v += __shfl_down_sync(0xFFFFFFFFu, v, off);
    int lane = threadIdx.x & 31;
    int wid  = threadIdx.x >> 5;
    if (lane == 0) smem[wid] = v;
    __syncthreads();
    int nwarps = (blockDim.x + 31) >> 5;
    v = (threadIdx.x < nwarps) ? smem[threadIdx.x] : 0.0f;
    if (wid == 0) {
        #pragma unroll
        for (int off = 16; off > 0; off >>= 1)
            v += __shfl_down_sync(0xFFFFFFFFu, v, off);
    }
    return v;  // valid in thread 0
}

__device__ __forceinline__ void quat2mat9(float q0, float q1, float q2, float q3,
                                          float* m) {
    m[0] = q0*q0 + q1*q1 - q2*q2 - q3*q3;
    m[1] = 2.0f * (q1*q2 - q0*q3);
    m[2] = 2.0f * (q1*q3 + q0*q2);
    m[3] = 2.0f * (q1*q2 + q0*q3);
    m[4] = q0*q0 - q1*q1 + q2*q2 - q3*q3;
    m[5] = 2.0f * (q2*q3 - q0*q1);
    m[6] = 2.0f * (q1*q3 - q0*q2);
    m[7] = 2.0f * (q2*q3 + q0*q1);
    m[8] = q0*q0 - q1*q1 - q2*q2 + q3*q3;
}

__global__ void __launch_bounds__(TPB)
hp_fused(const float4* __restrict__ conf,
         const float4* __restrict__ gt,
         const float4* __restrict__ wgt,
         const float* __restrict__ dr,    // [N,5]
         const float* __restrict__ ann,   // [N,5]
         const int* __restrict__ flags,   // [N] bool-as-int32
         int n4, int N) {
    __shared__ float smem[32];
    int b = blockIdx.x;

    if (b < NBLK_CONF) {
        // ------- confidence partial reduction (HBM-bound) -------
        float acc = 0.0f;
        int stride = NBLK_CONF * TPB;
        for (int i = b * TPB + threadIdx.x; i < n4; i += stride) {
            float4 c = conf[i];
            float4 g = gt[i];
            float4 w = wgt[i];
            float d0 = c.x - g.x, d1 = c.y - g.y, d2 = c.z - g.z, d3 = c.w - g.w;
            acc = fmaf(w.x, d0 * d0, acc);
            acc = fmaf(w.y, d1 * d1, acc);
            acc = fmaf(w.z, d2 * d2, acc);
            acc = fmaf(w.w, d3 * d3, acc);
        }
        float total = block_reduce_sum(acc, smem);
        if (threadIdx.x == 0) g_conf_part[b] = total;
    } else {
        // ------- ann losses: one thread per item -------
        int ab = b - NBLK_CONF;
        int i = ab * TPB + threadIdx.x;
        float dsum = 0.0f, rsum = 0.0f;
        if (i < N && flags[i] != 0) {
            const float* drp  = dr  + i * 5;
            const float* annp = ann + i * 5;
            float dd = drp[0] - annp[0];
            dsum = dd * dd;

            float mp[9];
            quat2mat9(annp[1], annp[2], annp[3], annp[4], mp);

            float q0 = drp[1], q1 = drp[2], q2 = drp[3], q3 = drp[4];
            float inv = rsqrtf(q0*q0 + q1*q1 + q2*q2 + q3*q3);
            float mg[9];
            quat2mat9(q0 * inv, q1 * inv, q2 * inv, q3 * inv, mg);

            // RY = diag(-1,1,-1): m_pred @ RY negates columns 0 and 2
            float s1 = 0.0f, s2 = 0.0f;
            #pragma unroll
            for (int k = 0; k < 9; k++) {
                int col = k % 3;
                float e1 = mg[k] - mp[k];
                float mpr = (col == 1) ? mp[k] : -mp[k];
                float e2 = mg[k] - mpr;
                s1 = fmaf(e1, e1, s1);
                s2 = fmaf(e2, e2, s2);
            }
            rsum = fminf(sqrtf(s1), sqrtf(s2));
        }
        float dtot = block_reduce_sum(dsum, smem);
        __syncthreads();
        float rtot = block_reduce_sum(rsum, smem);
        if (threadIdx.x == 0) {
            g_depth_part[ab] = dtot;
            g_rot_part[ab]   = rtot;
        }
    }
}

__global__ void __launch_bounds__(1024)
hp_finish(float* __restrict__ out, int N) {
    __shared__ float smem[32];
    int t = threadIdx.x;

    // conf partials
    float v = 0.0f;
    for (int i = t; i < NBLK_CONF; i += 1024) v += g_conf_part[i];
    float conf_total = block_reduce_sum(v, smem);
    __syncthreads();

    // depth partials
    v = (t < NBLK_ANN) ? g_depth_part[t] : 0.0f;
    float depth_total = block_reduce_sum(v, smem);
    __syncthreads();

    // rotation partials
    v = (t < NBLK_ANN) ? g_rot_part[t] : 0.0f;
    float rot_total = block_reduce_sum(v, smem);

    if (t == 0) {
        float invN = 1.0f / (float)N;
        out[0] = conf_total * (1.0f / 65536.0f);
        out[1] = depth_total * invN;
        out[2] = rot_total * invN;
    }
}

extern "C" void kernel_launch(void* const* d_in, const int* in_sizes, int n_in,
                              void* d_out, int out_size) {
    const float* conf = (const float*)d_in[0];   // (256,1,256,256)
    const float* gt   = (const float*)d_in[1];   // (256,1,256,256)
    const float* wgt  = (const float*)d_in[2];   // (256,256,256)
    const float* dr   = (const float*)d_in[3];   // (8192,5)
    const float* ann  = (const float*)d_in[4];   // (8192,5)
    const int* flags  = (const int*)d_in[5];     // (8192,) bool as int32

    float* out = (float*)d_out;
    int n_conf = in_sizes[0];      // 16777216
    int n4 = n_conf >> 2;
    int N = in_sizes[5];           // 8192

    hp_fused<<<NBLK_CONF + NBLK_ANN, TPB>>>(
        (const float4*)conf, (const float4*)gt, (const float4*)wgt,
        dr, ann, flags, n4, N);

    hp_finish<<<1, 1024>>>(out, N);
}